// round 6
// baseline (speedup 1.0000x reference)
#include <cuda_runtime.h>
#include <math.h>
#include <stdint.h>

#define EMBED 1024
#define HEADS 16
#define DKH 64
#define BATCH 2
#define SEQ 2048
#define MTOT (BATCH * SEQ)  // 4096
#define WSZ (EMBED * EMBED) // 1048576

// ---- mma.sync tf32 GEMM tiling ----
#define BK 32
#define NCH (EMBED / BK)
#define ASTR 40                  // A smem stride: float2 frag loads conflict-free
#define BSTR 132                 // B smem stride: re-paired scalar loads conflict-free
#define ABYTES (128 * ASTR * 4)  // 20480
#define BBYTES (BK * BSTR * 4)   // 16896
#define STAGEB (ABYTES + BBYTES) // 37376
#define GSMEM (2 * STAGEB)       // 74752 (>= epilogue 73728)

// ---- flash-TC smem layout (floats) ----
#define FKST 72
#define FQST 68
#define FK0 0
#define FK1 (64 * FKST)         // 4608
#define FV0 (2 * 64 * FKST)     // 9216
#define FV1 (FV0 + 64 * FKST)   // 13824
#define FP (FV0 + 2 * 64 * FKST)// 18432
#define FSMEM ((FP + 128 * FQST) * 4)  // 108544 bytes

// Scratch (allocation-free rule: __device__ globals)
__device__ float g_q[(size_t)BATCH * HEADS * SEQ * DKH];
__device__ float g_k[(size_t)BATCH * HEADS * SEQ * DKH];
__device__ float g_v[(size_t)BATCH * HEADS * SEQ * DKH];
__device__ float g_attn[(size_t)MTOT * EMBED];
__device__ float g_xr[(size_t)MTOT * EMBED];  // tf32-rounded x
__device__ float g_w4[(size_t)4 * WSZ];       // tf32-rounded wq|wk|wv|wo
__device__ float2 g_rope[(size_t)SEQ * 32];

// ---------------------------------------------------------------------------
// helpers
// ---------------------------------------------------------------------------
__device__ __forceinline__ uint32_t su32(const void* p) {
    uint32_t a;
    asm("{ .reg .u64 t; cvta.to.shared.u64 t, %1; cvt.u32.u64 %0, t; }"
        : "=r"(a) : "l"(p));
    return a;
}

__device__ __forceinline__ void cp16(uint32_t dst, const void* src) {
    asm volatile("cp.async.cg.shared.global [%0], [%1], 16;" :: "r"(dst), "l"(src));
}

__device__ __forceinline__ uint32_t cvt_tf32(float x) {
    uint32_t r;
    asm("cvt.rna.tf32.f32 %0, %1;" : "=r"(r) : "f"(x));
    return r;
}

__device__ __forceinline__ float tfr(float x) {
    return __uint_as_float(cvt_tf32(x));
}

__device__ __forceinline__ void mma8(float* d, const uint32_t* a, const uint32_t* b) {
    asm volatile(
        "mma.sync.aligned.m16n8k8.row.col.f32.tf32.tf32.f32 "
        "{%0,%1,%2,%3}, {%4,%5,%6,%7}, {%8,%9}, {%0,%1,%2,%3};"
        : "+f"(d[0]), "+f"(d[1]), "+f"(d[2]), "+f"(d[3])
        : "r"(a[0]), "r"(a[1]), "r"(a[2]), "r"(a[3]), "r"(b[0]), "r"(b[1]));
}

// ---------------------------------------------------------------------------
// prep kernels
// ---------------------------------------------------------------------------
__global__ void rope_table_kernel() {
    int idx = blockIdx.x * 256 + threadIdx.x;
    int s = idx >> 5, p = idx & 31;
    double inv = 1.0 / pow(10000.0, (double)(2 * p) / 64.0);
    float ang = (float)s * (float)inv;
    g_rope[idx] = make_float2(cosf(ang), sinf(ang));
}

__global__ void __launch_bounds__(256) roundcopy(float* __restrict__ dst,
                                                 const float* __restrict__ src,
                                                 int n4) {
    int i = blockIdx.x * 256 + threadIdx.x;
    if (i < n4) {
        float4 v = ((const float4*)src)[i];
        v.x = tfr(v.x);
        v.y = tfr(v.y);
        v.z = tfr(v.z);
        v.w = tfr(v.w);
        ((float4*)dst)[i] = v;
    }
}

// ---------------------------------------------------------------------------
// mma.sync tf32 GEMM. Inputs pre-rounded to tf32 -> no cvt in the hot loop.
// Fragment k-pairing: (k_lo, k_hi) = (2gc, 2gc+1) so A frags are float2 loads.
// CTA 128x128, BK=32, 8 warps (2x4), warp tile 64x32.
// ---------------------------------------------------------------------------
template <int MODE>
__global__ void __launch_bounds__(256) gemm_mma(const float* __restrict__ A,
                                                const float* __restrict__ w0,
                                                const float* __restrict__ w1,
                                                const float* __restrict__ w2,
                                                float* __restrict__ d0,
                                                float* __restrict__ d1,
                                                float* __restrict__ d2) {
    extern __shared__ float sm[];

    const int tid = threadIdx.x;
    const int lane = tid & 31, wid = tid >> 5;
    const int wm = wid >> 2, wn = wid & 3;
    const int gr = lane >> 2, gc = lane & 3;
    const int n0 = blockIdx.x * 128;
    const int m0 = blockIdx.y * 128;

    const float* W;
    float* dst;
    int rope;
    if (MODE == 1) {
        int z = blockIdx.z;
        W = z == 0 ? w0 : (z == 1 ? w1 : w2);
        dst = z == 0 ? d0 : (z == 1 ? d1 : d2);
        rope = (z < 2);
    } else {
        W = w0;
        dst = d0;
        rope = 0;
    }

    const uint32_t smb = su32(sm);

    auto fill = [&](int s, int kc) {
        uint32_t ab = smb + (uint32_t)s * STAGEB;
        uint32_t bb = ab + ABYTES;
#pragma unroll
        for (int it = 0; it < 4; it++) {
            int idx = tid + it * 256;
            int r = idx >> 3, c4 = idx & 7;
            cp16(ab + (uint32_t)(r * (ASTR * 4) + c4 * 16),
                 A + (size_t)(m0 + r) * EMBED + kc + c4 * 4);
        }
#pragma unroll
        for (int it = 0; it < 4; it++) {
            int idx = tid + it * 256;
            int r = idx >> 5, c4 = idx & 31;
            cp16(bb + (uint32_t)(r * (BSTR * 4) + c4 * 16),
                 W + (size_t)(kc + r) * EMBED + n0 + c4 * 4);
        }
        asm volatile("cp.async.commit_group;" ::: "memory");
    };

    float acc[4][4][4];
#pragma unroll
    for (int mi = 0; mi < 4; mi++)
#pragma unroll
        for (int ni = 0; ni < 4; ni++)
#pragma unroll
            for (int r = 0; r < 4; r++) acc[mi][ni][r] = 0.f;

    fill(0, 0);

    for (int i = 0; i < NCH; i++) {
        if (i + 1 < NCH) {
            fill((i + 1) & 1, (i + 1) * BK);
            asm volatile("cp.async.wait_group 1;" ::: "memory");
        } else {
            asm volatile("cp.async.wait_group 0;" ::: "memory");
        }
        __syncthreads();

        const float* Asb = sm + (i & 1) * (STAGEB / 4);
        const float* Bsb = Asb + 128 * ASTR;

#pragma unroll
        for (int ks = 0; ks < 4; ks++) {
            const int kb = ks * 8;
            uint32_t af[4][4], bf[4][2];
#pragma unroll
            for (int mi = 0; mi < 4; mi++) {
                int r0 = wm * 64 + mi * 16 + gr;
                float2 a0 = *(const float2*)&Asb[r0 * ASTR + kb + 2 * gc];
                float2 a1 = *(const float2*)&Asb[(r0 + 8) * ASTR + kb + 2 * gc];
                af[mi][0] = __float_as_uint(a0.x);
                af[mi][1] = __float_as_uint(a1.x);
                af[mi][2] = __float_as_uint(a0.y);
                af[mi][3] = __float_as_uint(a1.y);
            }
#pragma unroll
            for (int ni = 0; ni < 4; ni++) {
                int c0 = wn * 32 + ni * 8 + gr;
                bf[ni][0] = __float_as_uint(Bsb[(kb + 2 * gc) * BSTR + c0]);
                bf[ni][1] = __float_as_uint(Bsb[(kb + 2 * gc + 1) * BSTR + c0]);
            }
#pragma unroll
            for (int mi = 0; mi < 4; mi++)
#pragma unroll
                for (int ni = 0; ni < 4; ni++)
                    mma8(acc[mi][ni], af[mi], bf[ni]);
        }
        __syncthreads();
    }

    if (rope) {
#pragma unroll
        for (int mi = 0; mi < 4; mi++)
#pragma unroll
            for (int h2 = 0; h2 < 2; h2++) {
                int row = m0 + wm * 64 + mi * 16 + gr + h2 * 8;
                int s = row & (SEQ - 1);
#pragma unroll
                for (int ni = 0; ni < 4; ni++) {
                    int col = n0 + wn * 32 + ni * 8 + gc * 2;
                    int p = (col & 63) >> 1;
                    float2 cs = g_rope[(size_t)s * 32 + p];
                    float e = acc[mi][ni][h2 * 2 + 0];
                    float o = acc[mi][ni][h2 * 2 + 1];
                    acc[mi][ni][h2 * 2 + 0] = e * cs.x - o * cs.y;
                    acc[mi][ni][h2 * 2 + 1] = o * cs.x + e * cs.y;
                }
            }
    }

    float* stg = sm + wid * (64 * 36);
#pragma unroll
    for (int mi = 0; mi < 4; mi++)
#pragma unroll
        for (int ni = 0; ni < 4; ni++)
#pragma unroll
            for (int h2 = 0; h2 < 2; h2++) {
                int rl = mi * 16 + gr + h2 * 8;
                int cl = ni * 8 + gc * 2;
                float v0 = acc[mi][ni][h2 * 2], v1 = acc[mi][ni][h2 * 2 + 1];
                if (MODE == 1) {  // tf32-round q/k/v at rest
                    v0 = tfr(v0);
                    v1 = tfr(v1);
                }
                *(float2*)&stg[rl * 36 + cl] = make_float2(v0, v1);
            }
    __syncwarp();

    const int lr = lane >> 3, c4 = lane & 7;
    if (MODE == 0) {
#pragma unroll
        for (int it = 0; it < 16; it++) {
            int rl = it * 4 + lr;
            float4 v = *(float4*)&stg[rl * 36 + c4 * 4];
            int row = m0 + wm * 64 + rl;
            *(float4*)&dst[(size_t)row * EMBED + n0 + wn * 32 + c4 * 4] = v;
        }
    } else {
        const int ncol = n0 + wn * 32;
        const int h = ncol >> 6, dbase = ncol & 63;
#pragma unroll
        for (int it = 0; it < 16; it++) {
            int rl = it * 4 + lr;
            float4 v = *(float4*)&stg[rl * 36 + c4 * 4];
            int row = m0 + wm * 64 + rl;
            int b = row >> 11;
            int s = row & (SEQ - 1);
            *(float4*)&dst[(((size_t)(b * HEADS + h)) * SEQ + s) * DKH + dbase + c4 * 4] = v;
        }
    }
}

// ---------------------------------------------------------------------------
// Tensor-core flash attention, causal. CTA: 128 q-rows, 8 warps (16 rows each),
// KV tiles of 64 double-buffered. K frag loads re-paired -> float2 (stride 72).
// PV path keeps the original (gc, gc+4) pairing. Output tf32-rounded for wo.
// ---------------------------------------------------------------------------
__global__ void __launch_bounds__(256) flash_tc(const float* __restrict__ Q,
                                                const float* __restrict__ Kk,
                                                const float* __restrict__ V,
                                                float* __restrict__ Out) {
    extern __shared__ float fs[];
    const int tid = threadIdx.x;
    const int lane = tid & 31, w = tid >> 5;
    const int gr = lane >> 2, gc = lane & 3;
    const int qi = gridDim.x - 1 - blockIdx.x;  // long blocks launch first
    const int bh = blockIdx.y;
    const int nt = 2 * qi + 2;  // kv tiles of 64

    const float* Qb = Q + ((size_t)bh * SEQ + (size_t)qi * 128) * DKH;
    const float* Kb = Kk + (size_t)bh * SEQ * DKH;
    const float* Vb = V + (size_t)bh * SEQ * DKH;

    auto fillkv = [&](int buf, int j) {
        uint32_t kd = su32(fs + (buf ? FK1 : FK0));
        uint32_t vd = su32(fs + (buf ? FV1 : FV0));
        const float* ks = Kb + (size_t)j * 64 * DKH;
        const float* vs = Vb + (size_t)j * 64 * DKH;
#pragma unroll
        for (int it = 0; it < 4; it++) {
            int idx = tid + it * 256;
            int r = idx >> 4, c4 = idx & 15;
            cp16(kd + (uint32_t)(r * 288 + c4 * 16), ks + r * 64 + c4 * 4);
        }
#pragma unroll
        for (int it = 0; it < 4; it++) {
            int idx = tid + it * 256;
            int r = idx >> 4, c4 = idx & 15;
            cp16(vd + (uint32_t)(r * 288 + c4 * 16), vs + r * 64 + c4 * 4);
        }
        asm volatile("cp.async.commit_group;" ::: "memory");
    };

    // Q tile (128x64) into the P region; grouped with K0/V0
    {
        uint32_t qd = su32(fs + FP);
#pragma unroll
        for (int it = 0; it < 8; it++) {
            int idx = tid + it * 256;
            int r = idx >> 4, c4 = idx & 15;
            cp16(qd + (uint32_t)(r * 272 + c4 * 16), Qb + r * 64 + c4 * 4);
        }
    }
    fillkv(0, 0);
    fillkv(1, 1);  // nt >= 2 always

    asm volatile("cp.async.wait_group 1;" ::: "memory");
    __syncthreads();

    // Q fragments (persist in registers), re-paired (2gc, 2gc+1)
    uint32_t qf[8][4];
    {
        const float* Pq = fs + FP;
        int r0 = w * 16 + gr;
#pragma unroll
        for (int ks = 0; ks < 8; ks++) {
            float2 qa = *(const float2*)&Pq[r0 * FQST + ks * 8 + 2 * gc];
            float2 qb2 = *(const float2*)&Pq[(r0 + 8) * FQST + ks * 8 + 2 * gc];
            qf[ks][0] = __float_as_uint(qa.x);
            qf[ks][1] = __float_as_uint(qb2.x);
            qf[ks][2] = __float_as_uint(qa.y);
            qf[ks][3] = __float_as_uint(qb2.y);
        }
    }
    __syncthreads();  // P region now reusable

    float miA = -1e30f, miB = -1e30f, liA = 0.f, liB = 0.f;
    float oacc[8][4];
#pragma unroll
    for (int n8 = 0; n8 < 8; n8++)
#pragma unroll
        for (int r = 0; r < 4; r++) oacc[n8][r] = 0.f;

    float* Pw = fs + FP + w * (16 * FQST);
    const int wrow = qi * 128 + w * 16;  // this warp's first q row

    for (int j = 0; j < nt; j++) {
        if (j <= nt - 2)
            asm volatile("cp.async.wait_group 1;" ::: "memory");
        else
            asm volatile("cp.async.wait_group 0;" ::: "memory");
        __syncthreads();

        const float* Ks = fs + ((j & 1) ? FK1 : FK0);
        const float* Vs = fs + ((j & 1) ? FV1 : FV0);

        if (j * 64 <= wrow + 15) {  // tile not fully masked for this warp
            float sacc[8][4];
#pragma unroll
            for (int n8 = 0; n8 < 8; n8++)
#pragma unroll
                for (int r = 0; r < 4; r++) sacc[n8][r] = 0.f;

#pragma unroll
            for (int ks = 0; ks < 8; ks++) {
#pragma unroll
                for (int n8 = 0; n8 < 8; n8++) {
                    float2 kv2 = *(const float2*)&Ks[(n8 * 8 + gr) * FKST + ks * 8 + 2 * gc];
                    uint32_t bf[2] = {__float_as_uint(kv2.x), __float_as_uint(kv2.y)};
                    mma8(sacc[n8], qf[ks], bf);
                }
            }

            if (j * 64 + 63 > wrow) {  // diagonal-crossing: mask
                int r0 = wrow + gr;
#pragma unroll
                for (int n8 = 0; n8 < 8; n8++) {
                    int c = j * 64 + n8 * 8 + 2 * gc;
                    sacc[n8][0] = (c > r0) ? -1e30f : sacc[n8][0] * 0.125f;
                    sacc[n8][1] = (c + 1 > r0) ? -1e30f : sacc[n8][1] * 0.125f;
                    sacc[n8][2] = (c > r0 + 8) ? -1e30f : sacc[n8][2] * 0.125f;
                    sacc[n8][3] = (c + 1 > r0 + 8) ? -1e30f : sacc[n8][3] * 0.125f;
                }
            } else {
#pragma unroll
                for (int n8 = 0; n8 < 8; n8++)
#pragma unroll
                    for (int r = 0; r < 4; r++) sacc[n8][r] *= 0.125f;
            }

            // online softmax (rows gr and gr+8)
            float mA = -1e30f, mB = -1e30f;
#pragma unroll
            for (int n8 = 0; n8 < 8; n8++) {
                mA = fmaxf(mA, fmaxf(sacc[n8][0], sacc[n8][1]));
                mB = fmaxf(mB, fmaxf(sacc[n8][2], sacc[n8][3]));
            }
            mA = fmaxf(mA, __shfl_xor_sync(0xffffffffu, mA, 1));
            mA = fmaxf(mA, __shfl_xor_sync(0xffffffffu, mA, 2));
            mB = fmaxf(mB, __shfl_xor_sync(0xffffffffu, mB, 1));
            mB = fmaxf(mB, __shfl_xor_sync(0xffffffffu, mB, 2));

            float mnA = fmaxf(miA, mA), mnB = fmaxf(miB, mB);
            float aA = __expf(miA - mnA), aB = __expf(miB - mnB);
            float sA = 0.f, sB = 0.f;
#pragma unroll
            for (int n8 = 0; n8 < 8; n8++) {
                float p0 = __expf(sacc[n8][0] - mnA);
                float p1 = __expf(sacc[n8][1] - mnA);
                float p2 = __expf(sacc[n8][2] - mnB);
                float p3 = __expf(sacc[n8][3] - mnB);
                sA += p0 + p1;
                sB += p2 + p3;
                *(float2*)&Pw[gr * FQST + n8 * 8 + 2 * gc] = make_float2(tfr(p0), tfr(p1));
                *(float2*)&Pw[(gr + 8) * FQST + n8 * 8 + 2 * gc] = make_float2(tfr(p2), tfr(p3));
            }
            sA += __shfl_xor_sync(0xffffffffu, sA, 1);
            sA += __shfl_xor_sync(0xffffffffu, sA, 2);
            sB += __shfl_xor_sync(0xffffffffu, sB, 1);
            sB += __shfl_xor_sync(0xffffffffu, sB, 2);
            liA = liA * aA + sA;
            liB = liB * aB + sB;
            miA = mnA;
            miB = mnB;
#pragma unroll
            for (int n8 = 0; n8 < 8; n8++) {
                oacc[n8][0] *= aA;
                oacc[n8][1] *= aA;
                oacc[n8][2] *= aB;
                oacc[n8][3] *= aB;
            }
            __syncwarp();

            // O += P V (original (gc, gc+4) pairing)
#pragma unroll
            for (int ks = 0; ks < 8; ks++) {
                uint32_t af[4];
                af[0] = __float_as_uint(Pw[gr * FQST + ks * 8 + gc]);
                af[1] = __float_as_uint(Pw[(gr + 8) * FQST + ks * 8 + gc]);
                af[2] = __float_as_uint(Pw[gr * FQST + ks * 8 + gc + 4]);
                af[3] = __float_as_uint(Pw[(gr + 8) * FQST + ks * 8 + gc + 4]);
#pragma unroll
                for (int n8 = 0; n8 < 8; n8++) {
                    uint32_t bf[2];
                    bf[0] = __float_as_uint(Vs[(ks * 8 + gc) * FKST + n8 * 8 + gr]);
                    bf[1] = __float_as_uint(Vs[(ks * 8 + gc + 4) * FKST + n8 * 8 + gr]);
                    mma8(oacc[n8], af, bf);
                }
            }
        }

        __syncthreads();  // all warps done with K/V buffers
        if (j + 2 < nt) fillkv(j & 1, j + 2);
    }

    // epilogue: normalize, tf32-round, write [B,S,E]
    const int b = bh >> 4, h = bh & 15;
    const int row = wrow + gr;
    float invA = 1.f / liA, invB = 1.f / liB;
    float* o0 = Out + ((size_t)b * SEQ + row) * EMBED + h * 64;
    float* o1 = Out + ((size_t)b * SEQ + row + 8) * EMBED + h * 64;
#pragma unroll
    for (int n8 = 0; n8 < 8; n8++) {
        *(float2*)&o0[n8 * 8 + 2 * gc] =
            make_float2(tfr(oacc[n8][0] * invA), tfr(oacc[n8][1] * invA));
        *(float2*)&o1[n8 * 8 + 2 * gc] =
            make_float2(tfr(oacc[n8][2] * invB), tfr(oacc[n8][3] * invB));
    }
}

extern "C" void kernel_launch(void* const* d_in, const int* in_sizes, int n_in,
                              void* d_out, int out_size) {
    (void)in_sizes;
    (void)n_in;
    (void)out_size;
    const float* x = (const float*)d_in[0];
    const float* wq = (const float*)d_in[1];
    const float* wk = (const float*)d_in[2];
    const float* wv = (const float*)d_in[3];
    const float* wo = (const float*)d_in[4];
    float* out = (float*)d_out;

    float *q, *k, *v, *attn, *xr, *w4;
    cudaGetSymbolAddress((void**)&q, g_q);
    cudaGetSymbolAddress((void**)&k, g_k);
    cudaGetSymbolAddress((void**)&v, g_v);
    cudaGetSymbolAddress((void**)&attn, g_attn);
    cudaGetSymbolAddress((void**)&xr, g_xr);
    cudaGetSymbolAddress((void**)&w4, g_w4);

    cudaFuncSetAttribute(gemm_mma<1>, cudaFuncAttributeMaxDynamicSharedMemorySize, GSMEM);
    cudaFuncSetAttribute(gemm_mma<0>, cudaFuncAttributeMaxDynamicSharedMemorySize, GSMEM);
    cudaFuncSetAttribute(flash_tc, cudaFuncAttributeMaxDynamicSharedMemorySize, FSMEM);

    rope_table_kernel<<<SEQ * 32 / 256, 256>>>();
    roundcopy<<<(MTOT * EMBED / 4) / 256, 256>>>(xr, x, MTOT * EMBED / 4);
    roundcopy<<<(WSZ / 4) / 256, 256>>>(w4 + 0 * WSZ, wq, WSZ / 4);
    roundcopy<<<(WSZ / 4) / 256, 256>>>(w4 + 1 * WSZ, wk, WSZ / 4);
    roundcopy<<<(WSZ / 4) / 256, 256>>>(w4 + 2 * WSZ, wv, WSZ / 4);
    roundcopy<<<(WSZ / 4) / 256, 256>>>(w4 + 3 * WSZ, wo, WSZ / 4);

    gemm_mma<1><<<dim3(EMBED / 128, MTOT / 128, 3), 256, GSMEM>>>(
        xr, w4, w4 + WSZ, w4 + 2 * WSZ, q, k, v);
    flash_tc<<<dim3(SEQ / 128, BATCH * HEADS), 256, FSMEM>>>(q, k, v, attn);
    gemm_mma<0><<<dim3(EMBED / 128, MTOT / 128, 1), 256, GSMEM>>>(
        attn, w4 + 3 * WSZ, nullptr, nullptr, out, nullptr, nullptr);
}